// round 10
// baseline (speedup 1.0000x reference)
#include <cuda_runtime.h>
#include <cuda_fp16.h>
#include <cstdint>

// Problem constants
#define NB    4            // batches
#define NN    2048         // n = m per batch
#define DD    256          // feature dim
#define ITERS 50
#define MU    (1.0f/2048.0f)
#define STAB  1e-8f

// ---------------- device scratch (no allocations allowed) ----------------
static __device__ __align__(128) __half g_K[2ull * NB * NN * NN];   // 67 MB: [plan][b][i][j]
static __device__ __align__(16)  __half g_fn[3][8192ull * DD];      // normalized features
static __device__ float g_u[2][NB][NN];
static __device__ float g_c[3][2][NB][NN];                          // triple-buffered column sums
static __device__ float g_part[256];

__device__ __forceinline__ uint32_t smem_u32(const void* p) {
    return (uint32_t)__cvta_generic_to_shared(p);
}

// ---------------- 1) row-normalize features, cast to fp16; zero c[0] ----------------
__global__ void __launch_bounds__(256) norm_kernel(const float* __restrict__ s0,
                                                   const float* __restrict__ s1,
                                                   const float* __restrict__ s2) {
    int gt = blockIdx.x * blockDim.x + threadIdx.x;
    if (gt < 2 * NB * NN) ((float*)g_c[0])[gt] = 0.f;   // zero parity-0 accumulator

    int gw   = gt >> 5;             // global warp = row id
    int lane = threadIdx.x & 31;
    int which = gw >> 13;           // 0..2
    int row   = gw & 8191;
    const float* in = which == 0 ? s0 : (which == 1 ? s1 : s2);
    const float4* p = (const float4*)(in + (size_t)row * DD);
    float4 a = p[lane];
    float4 b = p[lane + 32];
    float ss = a.x*a.x + a.y*a.y + a.z*a.z + a.w*a.w
             + b.x*b.x + b.y*b.y + b.z*b.z + b.w*b.w;
    #pragma unroll
    for (int o = 16; o; o >>= 1) ss += __shfl_xor_sync(0xffffffffu, ss, o);
    float inv = 1.0f / (sqrtf(ss) + STAB);
    __half2* out = (__half2*)&g_fn[which][(size_t)row * DD];
    out[lane*2    ] = __floats2half2_rn(a.x*inv, a.y*inv);
    out[lane*2 + 1] = __floats2half2_rn(a.z*inv, a.w*inv);
    out[64 + lane*2    ] = __floats2half2_rn(b.x*inv, b.y*inv);
    out[64 + lane*2 + 1] = __floats2half2_rn(b.z*inv, b.w*inv);
}

// ---------------- 2) K = exp(dot - 1), fp16 tensor-core GEMM ----------------
__global__ void __launch_bounds__(256) gemm_exp_kernel() {
    int z = blockIdx.z;                 // 0..7: plan*4 + b
    int plan = z >> 2, b = z & 3;
    const __half* A  = &g_fn[plan    ][(size_t)b * NN * DD];
    const __half* Bm = &g_fn[plan + 1][(size_t)b * NN * DD];
    int row0 = blockIdx.y * 128, col0 = blockIdx.x * 128;

    __shared__ __align__(16) __half sA[128 * 72];
    __shared__ __align__(16) __half sB[128 * 72];

    int tid = threadIdx.x, warp = tid >> 5, lane = tid & 31;
    int wm = warp & 1;
    int wn = warp >> 1;

    float acc[4][4][4];
    #pragma unroll
    for (int i = 0; i < 4; i++)
        #pragma unroll
        for (int j = 0; j < 4; j++)
            #pragma unroll
            for (int k = 0; k < 4; k++) acc[i][j][k] = 0.f;

    for (int kc = 0; kc < 4; kc++) {
        #pragma unroll
        for (int i = 0; i < 4; i++) {
            int idx = tid + i * 256;
            int r = idx >> 3, c8 = (idx & 7) * 8;
            *(uint4*)&sA[r*72 + c8] = *(const uint4*)&A [(size_t)(row0 + r)*DD + kc*64 + c8];
            *(uint4*)&sB[r*72 + c8] = *(const uint4*)&Bm[(size_t)(col0 + r)*DD + kc*64 + c8];
        }
        __syncthreads();
        #pragma unroll
        for (int ks = 0; ks < 4; ks++) {
            uint32_t afr[4][4], bfr[4][2];
            #pragma unroll
            for (int mt = 0; mt < 4; mt++) {
                int r = wm*64 + mt*16 + (lane & 15);
                int c = ks*16 + (lane >> 4) * 8;
                uint32_t ad = smem_u32(&sA[r*72 + c]);
                asm volatile("ldmatrix.sync.aligned.m8n8.x4.shared.b16 {%0,%1,%2,%3}, [%4];"
                    : "=r"(afr[mt][0]), "=r"(afr[mt][1]), "=r"(afr[mt][2]), "=r"(afr[mt][3])
                    : "r"(ad));
            }
            #pragma unroll
            for (int nt = 0; nt < 4; nt++) {
                int r = wn*32 + nt*8 + (lane & 7);
                int c = ks*16 + ((lane >> 3) & 1) * 8;
                uint32_t ad = smem_u32(&sB[r*72 + c]);
                asm volatile("ldmatrix.sync.aligned.m8n8.x2.shared.b16 {%0,%1}, [%2];"
                    : "=r"(bfr[nt][0]), "=r"(bfr[nt][1]) : "r"(ad));
            }
            #pragma unroll
            for (int mt = 0; mt < 4; mt++)
                #pragma unroll
                for (int nt = 0; nt < 4; nt++)
                    asm volatile("mma.sync.aligned.m16n8k16.row.col.f32.f16.f16.f32 "
                        "{%0,%1,%2,%3}, {%4,%5,%6,%7}, {%8,%9}, {%0,%1,%2,%3};"
                        : "+f"(acc[mt][nt][0]), "+f"(acc[mt][nt][1]),
                          "+f"(acc[mt][nt][2]), "+f"(acc[mt][nt][3])
                        : "r"(afr[mt][0]), "r"(afr[mt][1]), "r"(afr[mt][2]), "r"(afr[mt][3]),
                          "r"(bfr[nt][0]), "r"(bfr[nt][1]));
        }
        __syncthreads();
    }

    __half* out = g_K + (size_t)z * NN * NN;
    #pragma unroll
    for (int mt = 0; mt < 4; mt++)
        #pragma unroll
        for (int nt = 0; nt < 4; nt++) {
            int r = row0 + wm*64 + mt*16 + (lane >> 2);
            int c = col0 + wn*32 + nt*8 + (lane & 3) * 2;
            __half2 h01 = __floats2half2_rn(__expf(acc[mt][nt][0] - 1.f),
                                            __expf(acc[mt][nt][1] - 1.f));
            __half2 h23 = __floats2half2_rn(__expf(acc[mt][nt][2] - 1.f),
                                            __expf(acc[mt][nt][3] - 1.f));
            *(__half2*)&out[(size_t)r      * NN + c] = h01;
            *(__half2*)&out[(size_t)(r + 8)* NN + c] = h23;
        }
}

// ---------------- 3) fused Sinkhorn iteration (single-wave shape) ----------------
// 512 CTAs x 256 threads, 4 CTAs/SM -> all CTAs resident in ONE wave
// (R8 shape: 512x512 @2/SM = 296 resident = 1.73 waves -> tail every launch).
// CTA = (plan, b, 32-row chunk).  Triple-buffered c.
//   Phase A: u = mu / (K v), warp handles 4 rows (DRAM/L2 read)
//   Phase B: thread owns 8 cols (uint4/row), re-reads the L2-hot block
__global__ void __launch_bounds__(256, 4) sink_iter(int iter) {
    int cta  = blockIdx.x;              // 512 CTAs
    int plan = cta >> 8;
    int b    = (cta >> 6) & 3;
    int ch   = cta & 63;                // 64 chunks x 32 rows

    __shared__ __align__(16) float sv[NN];
    __shared__ float su[32];
    int tid = threadIdx.x;

    // v from previous column sums (8 floats per thread)
    if (iter == 0) {
        #pragma unroll
        for (int k = 0; k < 8; k++) sv[tid + k * 256] = 1.f;
    } else {
        const float* c = g_c[(iter + 2) % 3][plan][b];
        float4 c0 = *(const float4*)&c[tid * 8];
        float4 c1 = *(const float4*)&c[tid * 8 + 4];
        float4 v0, v1;
        v0.x = MU/(c0.x+STAB); v0.y = MU/(c0.y+STAB); v0.z = MU/(c0.z+STAB); v0.w = MU/(c0.w+STAB);
        v1.x = MU/(c1.x+STAB); v1.y = MU/(c1.y+STAB); v1.z = MU/(c1.z+STAB); v1.w = MU/(c1.w+STAB);
        *(float4*)&sv[tid * 8]     = v0;
        *(float4*)&sv[tid * 8 + 4] = v1;
    }
    // zero the buffer the NEXT iteration will accumulate into
    if (tid < 32) ((float*)g_c[(iter + 1) % 3])[cta * 32 + tid] = 0.f;
    __syncthreads();

    int warp = tid >> 5, lane = tid & 31;
    const __half* Kb = g_K + ((size_t)(plan * NB + b)) * NN * NN;

    // Phase A: warp handles 4 rows (row-major dot with v)
    #pragma unroll
    for (int rr = 0; rr < 4; rr++) {
        int row = ch * 32 + warp * 4 + rr;
        const uint4* kp = (const uint4*)(Kb + (size_t)row * NN);
        float sum = 0.f;
        #pragma unroll
        for (int it = 0; it < 8; it++) {
            uint4 kv = kp[it * 32 + lane];
            int j = (it * 32 + lane) * 8;
            float4 v0 = *(const float4*)&sv[j];
            float4 v1 = *(const float4*)&sv[j + 4];
            float2 f0 = __half22float2(*(__half2*)&kv.x);
            float2 f1 = __half22float2(*(__half2*)&kv.y);
            float2 f2 = __half22float2(*(__half2*)&kv.z);
            float2 f3 = __half22float2(*(__half2*)&kv.w);
            sum += f0.x*v0.x + f0.y*v0.y + f1.x*v0.z + f1.y*v0.w
                 + f2.x*v1.x + f2.y*v1.y + f3.x*v1.z + f3.y*v1.w;
        }
        #pragma unroll
        for (int o = 16; o; o >>= 1) sum += __shfl_xor_sync(0xffffffffu, sum, o);
        if (lane == 0) {
            float uu = MU / (sum + STAB);
            su[warp * 4 + rr] = uu;
            g_u[plan][b][row] = uu;                  // consumed by loss_kernel
        }
    }
    __syncthreads();

    // Phase B: thread owns 8 columns (uint4/row), re-reads the L2-hot block
    const uint4* kp = (const uint4*)(Kb + (size_t)ch * 32 * NN) + tid;
    float a0 = 0.f, a1 = 0.f, a2 = 0.f, a3 = 0.f;
    float a4 = 0.f, a5 = 0.f, a6 = 0.f, a7 = 0.f;
    #pragma unroll
    for (int i = 0; i < 32; i++) {
        uint4 kv = kp[(size_t)i * 256];              // row stride = 2048 halves = 256 uint4
        float ui = su[i];
        float2 f0 = __half22float2(*(__half2*)&kv.x);
        float2 f1 = __half22float2(*(__half2*)&kv.y);
        float2 f2 = __half22float2(*(__half2*)&kv.z);
        float2 f3 = __half22float2(*(__half2*)&kv.w);
        a0 += f0.x*ui; a1 += f0.y*ui;
        a2 += f1.x*ui; a3 += f1.y*ui;
        a4 += f2.x*ui; a5 += f2.y*ui;
        a6 += f3.x*ui; a7 += f3.y*ui;
    }
    float* c = g_c[iter % 3][plan][b] + tid * 8;
    atomicAdd(&c[0], a0);
    atomicAdd(&c[1], a1);
    atomicAdd(&c[2], a2);
    atomicAdd(&c[3], a3);
    atomicAdd(&c[4], a4);
    atomicAdd(&c[5], a5);
    atomicAdd(&c[6], a6);
    atomicAdd(&c[7], a7);
}

// ---------------- 4) loss = sum |u1 K1 v1 - u2 K2 v2| ----------------
__global__ void __launch_bounds__(512) loss_kernel() {
    int cta  = blockIdx.x;              // 128 CTAs: b(4) x rowblk(32 of 64 rows)
    int b    = cta >> 5;
    int rblk = cta & 31;
    const int LASTBUF = (ITERS - 1) % 3;

    __shared__ __align__(16) float sv[2][NN];
    int tid = threadIdx.x;
    {
        float4 c1 = *(const float4*)&g_c[LASTBUF][0][b][tid * 4];
        float4 c2 = *(const float4*)&g_c[LASTBUF][1][b][tid * 4];
        float4 v1, v2;
        v1.x = MU/(c1.x+STAB); v1.y = MU/(c1.y+STAB); v1.z = MU/(c1.z+STAB); v1.w = MU/(c1.w+STAB);
        v2.x = MU/(c2.x+STAB); v2.y = MU/(c2.y+STAB); v2.z = MU/(c2.z+STAB); v2.w = MU/(c2.w+STAB);
        *(float4*)&sv[0][tid * 4] = v1;
        *(float4*)&sv[1][tid * 4] = v2;
    }
    __syncthreads();

    int warp = tid >> 5, lane = tid & 31;
    const __half* K1 = g_K + (size_t)b        * NN * NN;
    const __half* K2 = g_K + (size_t)(NB + b) * NN * NN;
    float sum = 0.f;
    #pragma unroll
    for (int rr = 0; rr < 4; rr++) {
        int row = rblk * 64 + warp * 4 + rr;
        float u1 = g_u[0][b][row];
        float u2 = g_u[1][b][row];
        const uint4* k1p = (const uint4*)(K1 + (size_t)row * NN);
        const uint4* k2p = (const uint4*)(K2 + (size_t)row * NN);
        #pragma unroll
        for (int it = 0; it < 8; it++) {
            uint4 a = k1p[it * 32 + lane];
            uint4 d = k2p[it * 32 + lane];
            int j = (it * 32 + lane) * 8;
            float4 w0 = *(const float4*)&sv[0][j];
            float4 w1 = *(const float4*)&sv[0][j + 4];
            float4 x0 = *(const float4*)&sv[1][j];
            float4 x1 = *(const float4*)&sv[1][j + 4];
            float2 a0 = __half22float2(*(__half2*)&a.x);
            float2 a1 = __half22float2(*(__half2*)&a.y);
            float2 a2 = __half22float2(*(__half2*)&a.z);
            float2 a3 = __half22float2(*(__half2*)&a.w);
            float2 d0 = __half22float2(*(__half2*)&d.x);
            float2 d1 = __half22float2(*(__half2*)&d.y);
            float2 d2 = __half22float2(*(__half2*)&d.z);
            float2 d3 = __half22float2(*(__half2*)&d.w);
            sum += fabsf(u1*a0.x*w0.x - u2*d0.x*x0.x);
            sum += fabsf(u1*a0.y*w0.y - u2*d0.y*x0.y);
            sum += fabsf(u1*a1.x*w0.z - u2*d1.x*x0.z);
            sum += fabsf(u1*a1.y*w0.w - u2*d1.y*x0.w);
            sum += fabsf(u1*a2.x*w1.x - u2*d2.x*x1.x);
            sum += fabsf(u1*a2.y*w1.y - u2*d2.y*x1.y);
            sum += fabsf(u1*a3.x*w1.z - u2*d3.x*x1.z);
            sum += fabsf(u1*a3.y*w1.w - u2*d3.y*x1.w);
        }
    }
    #pragma unroll
    for (int o = 16; o; o >>= 1) sum += __shfl_xor_sync(0xffffffffu, sum, o);
    __shared__ float swp[16];
    if (lane == 0) swp[warp] = sum;
    __syncthreads();
    if (warp == 0) {
        float t = (lane < 16) ? swp[lane] : 0.f;
        #pragma unroll
        for (int o = 8; o; o >>= 1) t += __shfl_xor_sync(0xffffffffu, t, o);
        if (lane == 0) g_part[cta] = t;
    }
}

__global__ void final_kernel(float* __restrict__ out) {
    int tid = threadIdx.x;  // 128 threads
    float s = g_part[tid];
    #pragma unroll
    for (int o = 16; o; o >>= 1) s += __shfl_xor_sync(0xffffffffu, s, o);
    __shared__ float sw[4];
    if ((tid & 31) == 0) sw[tid >> 5] = s;
    __syncthreads();
    if (tid == 0) {
        float t = sw[0] + sw[1] + sw[2] + sw[3];
        out[0] = t * (1.0f / (4.0f * 2048.0f * 2048.0f));
    }
}

// ---------------- host entry ----------------
extern "C" void kernel_launch(void* const* d_in, const int* in_sizes, int n_in,
                              void* d_out, int out_size) {
    (void)in_sizes; (void)n_in; (void)out_size;
    const float* src = (const float*)d_in[0];
    const float* tgt = (const float*)d_in[1];
    const float* gen = (const float*)d_in[2];

    norm_kernel<<<3072, 256>>>(src, tgt, gen);

    dim3 gg(16, 16, 8);
    gemm_exp_kernel<<<gg, 256>>>();

    for (int it = 0; it < ITERS; it++)
        sink_iter<<<512, 256>>>(it);

    loss_kernel<<<128, 512>>>();
    final_kernel<<<1, 128>>>((float*)d_out);
}